// round 2
// baseline (speedup 1.0000x reference)
#include <cuda_runtime.h>
#include <cuda_bf16.h>
#include <math.h>

#define HE 361
#define WE 720
#define LL 37
#define HM 180
#define WM 360
#define KK 32
#define NP 37
#define EPSV 1e-8f

#define XT 8                      // x positions per block
#define NTHREADS 256
#define HD_STRIDE 185             // 5*37 per x

#define OFF_PM  10368000L
#define OFF_PS  12441600L

__device__ __forceinline__ int ss_right_sh(const float* g, int n, float v) {
    // searchsorted(side='right'): first index m with g[m] > v
    int lo = 0, hi = n;
    while (lo < hi) {
        int m = (lo + hi) >> 1;
        if (g[m] <= v) lo = m + 1; else hi = m;
    }
    return lo;
}

// guess-then-fixup replacement for clip(searchsorted(grid, pt, 'right')-1, 0, n-2)
__device__ __forceinline__ int axis_idx(const float* __restrict__ grid, int n, float pt) {
    float g0 = __ldg(grid);
    float gN = __ldg(grid + n - 1);
    int i = (int)((pt - g0) / (gN - g0) * (float)(n - 1));
    i = min(max(i, 0), n - 2);
    while (i < n - 2 && __ldg(grid + i + 1) <= pt) i++;
    while (i > 0 && __ldg(grid + i) > pt) i--;
    return i;
}

__global__ __launch_bounds__(NTHREADS)
void era5_fused_kernel(const float* __restrict__ u,
                       const float* __restrict__ v,
                       const float* __restrict__ w,
                       const float* __restrict__ T,
                       const float* __restrict__ q,
                       const float* __restrict__ ps,
                       const float* __restrict__ era5_lat,
                       const float* __restrict__ era5_lon,
                       const float* __restrict__ model_lat,
                       const float* __restrict__ model_lon,
                       const float* __restrict__ p_levels,
                       const float* __restrict__ a_k,
                       const float* __restrict__ b_k,
                       float* __restrict__ out) {
    __shared__ float s_hd[XT * HD_STRIDE];   // horizontally-interped vars [x][v][l]
    __shared__ float s_lpe[NP];
    __shared__ float s_pl[NP];
    __shared__ float s_ak[KK], s_bk[KK];
    __shared__ int   s_ix[XT];
    __shared__ float s_tx[XT];
    __shared__ int   s_iy;
    __shared__ float s_ty;
    __shared__ float s_psm[XT];
    __shared__ int   s_nv[XT];

    const int tid = threadIdx.x;
    const int y = blockIdx.y;
    const int x0 = blockIdx.x * XT;

    // ---- phase 0: axis tables + constant tables ----
    if (tid < XT) {
        float pt = __ldg(model_lon + x0 + tid);
        int i = axis_idx(era5_lon, WE, pt);
        s_ix[tid] = i;
        s_tx[tid] = (pt - __ldg(era5_lon + i)) / (__ldg(era5_lon + i + 1) - __ldg(era5_lon + i));
    } else if (tid == 32) {
        float pt = __ldg(model_lat + y);
        int i = axis_idx(era5_lat, HE, pt);
        s_iy = i;
        s_ty = (pt - __ldg(era5_lat + i)) / (__ldg(era5_lat + i + 1) - __ldg(era5_lat + i));
    }
    if (tid >= 64 && tid < 64 + NP) {
        float pl = __ldg(p_levels + tid - 64);
        s_pl[tid - 64]  = pl;
        s_lpe[tid - 64] = logf(pl + EPSV);
    }
    if (tid >= 128 && tid < 128 + KK) {
        s_ak[tid - 128] = __ldg(a_k + tid - 128);
        s_bk[tid - 128] = __ldg(b_k + tid - 128);
    }
    __syncthreads();

    const int   iy = s_iy;
    const float ty = s_ty;

    // ---- phase 1a: surface pressure per x (threads 0..7) ----
    if (tid < XT) {
        int ix = s_ix[tid];
        float tx = s_tx[tid];
        int p00 = iy * WE + ix;
        float psm = (1.f - ty) * ((1.f - tx) * __ldg(ps + p00)      + tx * __ldg(ps + p00 + 1))
                  +        ty  * ((1.f - tx) * __ldg(ps + p00 + WE) + tx * __ldg(ps + p00 + WE + 1));
        s_psm[tid] = psm;
        s_nv[tid]  = ss_right_sh(s_pl, NP, psm);
    }

    // ---- phase 1b: horizontal bilinear of all 37 levels x 5 vars x 8 x's ----
    // flattened e = x*185 + v*37 + l  (l fastest -> coalesced column loads)
    #pragma unroll
    for (int e = tid; e < XT * HD_STRIDE; e += NTHREADS) {
        int xl = e / HD_STRIDE;
        int r  = e - xl * HD_STRIDE;
        int vv = r / LL;
        int l  = r - vv * LL;

        const float* __restrict__ a =
            (vv == 0) ? u : (vv == 1) ? v : (vv == 2) ? w : (vv == 3) ? T : q;

        int ix = s_ix[xl];
        float tx = s_tx[xl];
        int c00 = (iy * WE + ix) * LL + l;
        float d00 = __ldg(a + c00);
        float d01 = __ldg(a + c00 + LL);
        float d10 = __ldg(a + c00 + WE * LL);
        float d11 = __ldg(a + c00 + WE * LL + LL);
        s_hd[e] = (1.f - ty) * ((1.f - tx) * d00 + tx * d01)
                +        ty  * ((1.f - tx) * d10 + tx * d11);
    }
    __syncthreads();

    // ---- phase 2: vertical interp, entirely from shared ----
    const int k  = tid & (KK - 1);   // 0..31
    const int xl = tid >> 5;         // 0..7
    const int x  = x0 + xl;

    float psm = s_psm[xl];
    int   nv  = s_nv[xl];
    bool valid = (nv >= 2);

    float p  = s_ak[k] + s_bk[k] * psm;
    float lp = logf(p + EPSV);

    int idx = ss_right_sh(s_lpe, NP, lp) - 1;
    idx = min(max(idx, 0), max(nv - 2, 0));

    float lx0 = s_lpe[idx];
    float lx1 = s_lpe[idx + 1];
    float t   = (lp - lx0) / (lx1 - lx0);

    const float* hdx = s_hd + xl * HD_STRIDE;
    long obase = (((long)(y * WM + x)) * KK + k) * 5;

    float res[5];
    #pragma unroll
    for (int vi = 0; vi < 5; vi++) {
        float g0 = hdx[vi * LL + idx];
        float g1 = hdx[vi * LL + idx + 1];
        float o  = g0 + t * (g1 - g0);
        if (!valid) o = 0.f;            // mask BEFORE clip (matches reference)
        res[vi] = o;
    }
    res[3] = fminf(fmaxf(res[3], 150.f), 350.f);
    res[4] = fminf(fmaxf(res[4], 0.f), 0.05f);

    #pragma unroll
    for (int vi = 0; vi < 5; vi++)
        out[obase + vi] = res[vi];

    out[OFF_PM + ((long)(y * WM + x)) * KK + k] = p;

    if (k == 0)
        out[OFF_PS + (long)(y * WM + x)] = fminf(fmaxf(psm, 30000.f), 110000.f);
}

extern "C" void kernel_launch(void* const* d_in, const int* in_sizes, int n_in,
                              void* d_out, int out_size) {
    const float* u         = (const float*)d_in[0];
    const float* v         = (const float*)d_in[1];
    const float* w         = (const float*)d_in[2];
    const float* T         = (const float*)d_in[3];
    const float* q         = (const float*)d_in[4];
    const float* ps        = (const float*)d_in[5];
    const float* era5_lat  = (const float*)d_in[6];
    const float* era5_lon  = (const float*)d_in[7];
    const float* model_lat = (const float*)d_in[8];
    const float* model_lon = (const float*)d_in[9];
    const float* p_levels  = (const float*)d_in[10];
    const float* a_k       = (const float*)d_in[11];
    const float* b_k       = (const float*)d_in[12];
    float* out = (float*)d_out;

    dim3 block(NTHREADS);
    dim3 grid(WM / XT, HM);
    era5_fused_kernel<<<grid, block>>>(u, v, w, T, q, ps,
                                       era5_lat, era5_lon, model_lat, model_lon,
                                       p_levels, a_k, b_k, out);
}